// round 8
// baseline (speedup 1.0000x reference)
#include <cuda_runtime.h>
#include <cstdint>

// Problem shapes (fixed per reference setup_inputs)
#define BB 32
#define HH 1024
#define WW 1024
#define TH 512
#define TW 512
#define SS 256
#define NBLOCKS (128 * 32)   // grid (128, 32)

__device__ double g_img_sum = 0.0;
__device__ double g_stn_sum = 0.0;
__device__ unsigned int g_count = 0;

// Barrier-free fused kernel. Block (x = band*2 + half, b): 16 output rows x
// 512 cols. Each thread: 2 output cols x 16 rows, all operands in registers.
// Target cols k-1,k,k+1 x 10 rows loaded directly (L1 dedups neighbor overlap).
// No __syncthreads until the final block reduction.
__global__ __launch_bounds__(256, 3) void fused_kernel(const float* __restrict__ pred,
                                                       const float* __restrict__ tgt,
                                                       const int* __restrict__ pos,
                                                       const float* __restrict__ run,
                                                       float* __restrict__ out) {
    __shared__ float wsum[8];
    __shared__ float wsum2[8];

    const int band = blockIdx.x >> 1;    // 0..63
    const int h    = blockIdx.x & 1;     // 0 or 1
    const int b    = blockIdx.y;         // 0..31
    const int tid  = threadIdx.x;        // 0..255

    // ---- Front-batch target window: 3 cols x 10 rows into registers ----
    const int k  = 256 * h + tid;                    // center target col
    const int km = (k == 0)      ? 0      : k - 1;
    const int kp = (k == TW - 1) ? TW - 1 : k + 1;
    const int kr0 = band * 8 - 1;
    const float* tb = tgt + (size_t)b * TH * TW;

    float tm[10], t0[10], tp[10];
#pragma unroll
    for (int r = 0; r < 10; ++r) {
        int kr = kr0 + r;
        kr = kr < 0 ? 0 : (kr > TH - 1 ? TH - 1 : kr);
        const float* row = tb + (size_t)kr * TW;
        tm[r] = __ldg(row + km);
        t0[r] = __ldg(row + k);
        tp[r] = __ldg(row + kp);
    }

    // ---- Front-batch all 16 pred rows (float2, streaming) ----
    const float* pb = pred + ((size_t)b * HH + (size_t)band * 16) * WW + 512 * h + 2 * tid;
    float2 P[16];
#pragma unroll
    for (int r = 0; r < 16; ++r)
        P[r] = __ldcs((const float2*)(pb + (size_t)r * WW));

    // ---- Station loss (blockIdx.x==0 blocks only) ----
    float stn_val = 0.f;
    if (blockIdx.x == 0) {
        int idx = b * SS + tid;
        int px = pos[2 * idx];       // column
        int py = pos[2 * idx + 1];   // row
        const float* pb0 = pred + (size_t)b * HH * WW;
        float sum = 0.f;
        int cnt = 0;
#pragma unroll
        for (int dy = -1; dy <= 1; ++dy) {
            int y = py + dy;
            if ((unsigned)y < (unsigned)HH) {
#pragma unroll
                for (int dx = -1; dx <= 1; ++dx) {
                    int x = px + dx;
                    if ((unsigned)x < (unsigned)WW) {
                        sum += pb0[(size_t)y * WW + x];
                        cnt++;
                    }
                }
            }
        }
        float d = sum / (float)cnt - run[idx];
        stn_val = d * d;
    }

    // ---- Compute: all in registers, two independent acc chains ----
    float acc0 = 0.f, acc1 = 0.f;
#pragma unroll
    for (int p = 0; p < 8; ++p) {
        // even output row 2p: vertical 0.25*row(p) + 0.75*row(p+1)
        float vm = 0.25f * tm[p] + 0.75f * tm[p + 1];
        float v0 = 0.25f * t0[p] + 0.75f * t0[p + 1];
        float vp = 0.25f * tp[p] + 0.75f * tp[p + 1];
        float2 pv = P[2 * p];
        float d;
        d = pv.x - (0.25f * vm + 0.75f * v0); acc0 = fmaf(d, d, acc0);
        d = pv.y - (0.75f * v0 + 0.25f * vp); acc0 = fmaf(d, d, acc0);

        // odd output row 2p+1: vertical 0.75*row(p+1) + 0.25*row(p+2)
        vm = 0.75f * tm[p + 1] + 0.25f * tm[p + 2];
        v0 = 0.75f * t0[p + 1] + 0.25f * t0[p + 2];
        vp = 0.75f * tp[p + 1] + 0.25f * tp[p + 2];
        pv = P[2 * p + 1];
        d = pv.x - (0.25f * vm + 0.75f * v0); acc1 = fmaf(d, d, acc1);
        d = pv.y - (0.75f * v0 + 0.25f * vp); acc1 = fmaf(d, d, acc1);
    }
    float acc = acc0 + acc1;

    // ---- Block reductions (only barrier in the kernel) ----
#pragma unroll
    for (int o = 16; o > 0; o >>= 1) {
        acc     += __shfl_xor_sync(0xffffffffu, acc, o);
        stn_val += __shfl_xor_sync(0xffffffffu, stn_val, o);
    }
    int lane = tid & 31, wid = tid >> 5;
    if (lane == 0) { wsum[wid] = acc; wsum2[wid] = stn_val; }
    __syncthreads();

    if (tid == 0) {
        float s = 0.f, s2 = 0.f;
#pragma unroll
        for (int i = 0; i < 8; ++i) { s += wsum[i]; s2 += wsum2[i]; }
        atomicAdd(&g_img_sum, (double)s);
        if (blockIdx.x == 0) atomicAdd(&g_stn_sum, (double)s2);
        __threadfence();
        unsigned int old = atomicAdd(&g_count, 1u);
        if (old == NBLOCKS - 1) {
            double img = atomicAdd(&g_img_sum, 0.0) / (double)((size_t)BB * HH * WW);
            double stn = atomicAdd(&g_stn_sum, 0.0) / (double)(BB * SS);
            out[0] = (float)(img + 0.5 * stn);  // IMAGE_W=1.0, STATION_W=0.5
            out[1] = (float)img;
            out[2] = (float)stn;
            g_img_sum = 0.0;
            g_stn_sum = 0.0;
            __threadfence();
            g_count = 0u;
        }
    }
}

extern "C" void kernel_launch(void* const* d_in, const int* in_sizes, int n_in,
                              void* d_out, int out_size) {
    const float* pred = (const float*)d_in[0];   // (32,1,1024,1024) f32
    const float* tgt  = (const float*)d_in[1];   // (32,1,512,512) f32
    const int*   pos  = (const int*)d_in[2];     // (32,256,2) i32
    const float* run  = (const float*)d_in[3];   // (32,256) f32
    float* out = (float*)d_out;

    fused_kernel<<<dim3(128, BB), 256>>>(pred, tgt, pos, run, out);
}

// round 9
// speedup vs baseline: 1.1930x; 1.1930x over previous
#include <cuda_runtime.h>
#include <cstdint>

// Problem shapes (fixed per reference setup_inputs)
#define BB 32
#define HH 1024
#define WW 1024
#define TH 512
#define TW 512
#define SS 256
#define STCOLS 264           // staged target cols (4 halo + 256 + 4)
#define TSLOTS 66            // float4 slots per target row
#define NBLOCKS (128 * 32)   // grid (128, 32), 128-thread blocks

__device__ double g_img_sum = 0.0;
__device__ double g_stn_sum = 0.0;
__device__ unsigned int g_count = 0;

__device__ __forceinline__ void cp_async16(void* smem_dst, const void* gmem_src) {
    uint32_t s = (uint32_t)__cvta_generic_to_shared(smem_dst);
    asm volatile("cp.async.cg.shared.global [%0], [%1], 16;" :: "r"(s), "l"(gmem_src));
}

// Block (x = band*2 + half, b): 16 output rows x 512 cols, 128 threads.
// Each thread: 4 output cols x 16 rows, pred front-batched as 16 float4
// (256 B in flight per thread). Targets staged via cp.async.
__global__ __launch_bounds__(128, 5) void fused_kernel(const float* __restrict__ pred,
                                                       const float* __restrict__ tgt,
                                                       const int* __restrict__ pos,
                                                       const float* __restrict__ run,
                                                       float* __restrict__ out) {
    __shared__ float st[10][STCOLS];   // ~10.3 KB target staging
    __shared__ float wsum[4];
    __shared__ float wsum2[4];

    const int band = blockIdx.x >> 1;    // 0..63
    const int h    = blockIdx.x & 1;     // 0 or 1
    const int b    = blockIdx.y;         // 0..31
    const int tid  = threadIdx.x;        // 0..127
    const int kbase = band * 8 - 1;
    const int cbase = 256 * h - 4;       // global target col of smem idx 0

    // ---- Front-batch ALL 16 pred rows (float4, streaming) FIRST ----
    const float* pb = pred + ((size_t)b * HH + (size_t)band * 16) * WW + 512 * h + 4 * tid;
    float4 P[16];
#pragma unroll
    for (int r = 0; r < 16; ++r)
        P[r] = __ldcs((const float4*)(pb + (size_t)r * WW));

    // ---- Stage 10 target rows x 66 float4 via cp.async ----
    const float* tb = tgt + (size_t)b * TH * TW;
#pragma unroll
    for (int i = 0; i < 6; ++i) {
        int idx = tid + i * 128;              // 0..767
        if (idx < 10 * TSLOTS) {              // 660 slots
            int r = idx / TSLOTS;             // 0..9
            int s = idx - r * TSLOTS;         // 0..65
            int k = kbase + r;
            k = k < 0 ? 0 : (k > TH - 1 ? TH - 1 : k);
            int c = cbase + 4 * s;
            c = c < 0 ? 0 : (c > TW - 4 ? TW - 4 : c);  // OOB slots never read
            cp_async16(&st[r][4 * s], tb + (size_t)k * TW + c);
        }
    }
    asm volatile("cp.async.commit_group;");

    // ---- Station loss (blockIdx.x==0 blocks only; 2 stations/thread) ----
    float stn_val = 0.f;
    if (blockIdx.x == 0) {
        const float* pb0 = pred + (size_t)b * HH * WW;
#pragma unroll
        for (int si = 0; si < 2; ++si) {
            int idx = b * SS + tid + si * 128;
            int px = pos[2 * idx];       // column
            int py = pos[2 * idx + 1];   // row
            float sum = 0.f;
            int cnt = 0;
#pragma unroll
            for (int dy = -1; dy <= 1; ++dy) {
                int y = py + dy;
                if ((unsigned)y < (unsigned)HH) {
#pragma unroll
                    for (int dx = -1; dx <= 1; ++dx) {
                        int x = px + dx;
                        if ((unsigned)x < (unsigned)WW) {
                            sum += pb0[(size_t)y * WW + x];
                            cnt++;
                        }
                    }
                }
            }
            float d = sum / (float)cnt - run[idx];
            stn_val += d * d;
        }
    }

    asm volatile("cp.async.wait_group 0;");
    __syncthreads();

    // Target cols this thread blends around (global 2g-1..2g+2, g = 256h+2tid? no:
    // thread covers output cols 512h+4t..+3 -> target center pair g0=256h+2t, g0+1)
    const int g0 = 256 * h + 2 * tid;            // global target col (pair start)
    int q0 = g0 - 1; if (q0 < 0) q0 = 0;
    int q3 = g0 + 2; if (q3 > TW - 1) q3 = TW - 1;
    const int j0 = q0 - cbase;
    const int j1 = g0 - cbase;
    const int j2 = j1 + 1;
    const int j3 = q3 - cbase;

    float a0 = st[0][j0], a1 = st[0][j1], a2 = st[0][j2], a3 = st[0][j3];
    float b0 = st[1][j0], b1 = st[1][j1], b2 = st[1][j2], b3 = st[1][j3];

    float acc0 = 0.f, acc1 = 0.f;

#pragma unroll
    for (int p = 0; p < 8; ++p) {
        float c0 = st[p + 2][j0], c1 = st[p + 2][j1];
        float c2 = st[p + 2][j2], c3 = st[p + 2][j3];

        // even output row 2p: vertical 0.25*row(p) + 0.75*row(p+1)
        float4 pv = P[2 * p];
        float v0 = 0.25f * a0 + 0.75f * b0;
        float v1 = 0.25f * a1 + 0.75f * b1;
        float v2 = 0.25f * a2 + 0.75f * b2;
        float v3 = 0.25f * a3 + 0.75f * b3;
        float d;
        d = pv.x - (0.25f * v0 + 0.75f * v1); acc0 = fmaf(d, d, acc0);
        d = pv.y - (0.75f * v1 + 0.25f * v2); acc1 = fmaf(d, d, acc1);
        d = pv.z - (0.25f * v1 + 0.75f * v2); acc0 = fmaf(d, d, acc0);
        d = pv.w - (0.75f * v2 + 0.25f * v3); acc1 = fmaf(d, d, acc1);

        // odd output row 2p+1: vertical 0.75*row(p+1) + 0.25*row(p+2)
        pv = P[2 * p + 1];
        v0 = 0.75f * b0 + 0.25f * c0;
        v1 = 0.75f * b1 + 0.25f * c1;
        v2 = 0.75f * b2 + 0.25f * c2;
        v3 = 0.75f * b3 + 0.25f * c3;
        d = pv.x - (0.25f * v0 + 0.75f * v1); acc0 = fmaf(d, d, acc0);
        d = pv.y - (0.75f * v1 + 0.25f * v2); acc1 = fmaf(d, d, acc1);
        d = pv.z - (0.25f * v1 + 0.75f * v2); acc0 = fmaf(d, d, acc0);
        d = pv.w - (0.75f * v2 + 0.25f * v3); acc1 = fmaf(d, d, acc1);

        a0 = b0; a1 = b1; a2 = b2; a3 = b3;
        b0 = c0; b1 = c1; b2 = c2; b3 = c3;
    }
    float acc = acc0 + acc1;

    // ---- Block reductions (4 warps) ----
#pragma unroll
    for (int o = 16; o > 0; o >>= 1) {
        acc     += __shfl_xor_sync(0xffffffffu, acc, o);
        stn_val += __shfl_xor_sync(0xffffffffu, stn_val, o);
    }
    int lane = tid & 31, wid = tid >> 5;
    if (lane == 0) { wsum[wid] = acc; wsum2[wid] = stn_val; }
    __syncthreads();

    if (tid == 0) {
        float s  = wsum[0] + wsum[1] + wsum[2] + wsum[3];
        float s2 = wsum2[0] + wsum2[1] + wsum2[2] + wsum2[3];
        atomicAdd(&g_img_sum, (double)s);
        if (blockIdx.x == 0) atomicAdd(&g_stn_sum, (double)s2);
        __threadfence();
        unsigned int old = atomicAdd(&g_count, 1u);
        if (old == NBLOCKS - 1) {
            double img = atomicAdd(&g_img_sum, 0.0) / (double)((size_t)BB * HH * WW);
            double stn = atomicAdd(&g_stn_sum, 0.0) / (double)(BB * SS);
            out[0] = (float)(img + 0.5 * stn);  // IMAGE_W=1.0, STATION_W=0.5
            out[1] = (float)img;
            out[2] = (float)stn;
            g_img_sum = 0.0;
            g_stn_sum = 0.0;
            __threadfence();
            g_count = 0u;
        }
    }
}

extern "C" void kernel_launch(void* const* d_in, const int* in_sizes, int n_in,
                              void* d_out, int out_size) {
    const float* pred = (const float*)d_in[0];   // (32,1,1024,1024) f32
    const float* tgt  = (const float*)d_in[1];   // (32,1,512,512) f32
    const int*   pos  = (const int*)d_in[2];     // (32,256,2) i32
    const float* run  = (const float*)d_in[3];   // (32,256) f32
    float* out = (float*)d_out;

    fused_kernel<<<dim3(128, BB), 128>>>(pred, tgt, pos, run, out);
}